// round 1
// baseline (speedup 1.0000x reference)
#include <cuda_runtime.h>
#include <cstdint>

// Problem constants
#define T_DIM 512
#define B_DIM 128
#define I_DIM 512
#define H_DIM 1024
#define BH (B_DIM * H_DIM)

// ---------------- scratch (static device globals: allocation-free) ----------
__device__ float g_pre[T_DIM * B_DIM * H_DIM];            // 268 MB, reused for pre0 then pre1
__device__ float g_w0sum[I_DIM * H_DIM];                  // Wi0 + Ws0
__device__ float g_sx1[(T_DIM - 1) * B_DIM * I_DIM];      // moving-average input for layer 1
__device__ unsigned g_bar;                                // grid barrier counter

// ---------------- small elementwise kernels --------------------------------
__global__ void k_add(const float* __restrict__ a, const float* __restrict__ b,
                      float* __restrict__ o, int n) {
    int i = blockIdx.x * 256 + threadIdx.x;
    if (i < n) o[i] = a[i] + b[i];
}

__global__ void k_sx1(const float* __restrict__ x, float* __restrict__ o,
                      int n, int off) {
    int i = blockIdx.x * 256 + threadIdx.x;
    if (i < n) o[i] = 0.5f * (x[i] + x[i + off]);
}

__global__ void k_reset_bar() { g_bar = 0u; }

// ---------------- fp32 SIMT GEMM: C[M,N] = A[M,K] @ B[K,N] (+C if beta) -----
// All dims are multiples of the tile sizes for this problem -> no bounds checks.
#define GBM 128
#define GBN 128
#define GBK 8

__global__ __launch_bounds__(256) void sgemm_kernel(
    int M, int N, int K,
    const float* __restrict__ A, const float* __restrict__ Bm,
    float* __restrict__ C, int beta)
{
    __shared__ float As[GBK * GBM];
    __shared__ float Bs[GBK * GBN];
    const int tid = threadIdx.x;
    const int bx = blockIdx.x, by = blockIdx.y;
    const int trow = tid >> 4;           // 0..15
    const int tcol = tid & 15;           // 0..15
    const int aRow = tid >> 1;           // 0..127
    const int aCol = (tid & 1) * 4;      // 0 or 4
    const int bRow = tid >> 5;           // 0..7
    const int bCol = (tid & 31) * 4;     // 0..124

    const float* Ab = A + (size_t)by * GBM * K;
    const float* Bb = Bm + bx * GBN;

    float acc[8][8];
#pragma unroll
    for (int i = 0; i < 8; i++)
#pragma unroll
        for (int j = 0; j < 8; j++) acc[i][j] = 0.f;

    for (int k0 = 0; k0 < K; k0 += GBK) {
        float4 a4 = *(const float4*)(Ab + (size_t)aRow * K + k0 + aCol);
        As[(aCol + 0) * GBM + aRow] = a4.x;
        As[(aCol + 1) * GBM + aRow] = a4.y;
        As[(aCol + 2) * GBM + aRow] = a4.z;
        As[(aCol + 3) * GBM + aRow] = a4.w;
        *(float4*)&Bs[bRow * GBN + bCol] =
            *(const float4*)(Bb + (size_t)(k0 + bRow) * N + bCol);
        __syncthreads();
#pragma unroll
        for (int k = 0; k < GBK; k++) {
            float4 ra0 = *(const float4*)&As[k * GBM + trow * 8];
            float4 ra1 = *(const float4*)&As[k * GBM + trow * 8 + 4];
            float4 rb0 = *(const float4*)&Bs[k * GBN + tcol * 8];
            float4 rb1 = *(const float4*)&Bs[k * GBN + tcol * 8 + 4];
            float ra[8] = {ra0.x, ra0.y, ra0.z, ra0.w, ra1.x, ra1.y, ra1.z, ra1.w};
            float rb[8] = {rb0.x, rb0.y, rb0.z, rb0.w, rb1.x, rb1.y, rb1.z, rb1.w};
#pragma unroll
            for (int i = 0; i < 8; i++)
#pragma unroll
                for (int j = 0; j < 8; j++) acc[i][j] += ra[i] * rb[j];
        }
        __syncthreads();
    }

    float* Cb = C + (size_t)by * GBM * N + bx * GBN;
#pragma unroll
    for (int i = 0; i < 8; i++) {
        int r = trow * 8 + i;
#pragma unroll
        for (int j = 0; j < 8; j += 4) {
            float* cp = Cb + (size_t)r * N + tcol * 8 + j;
            float4 v = make_float4(acc[i][j], acc[i][j + 1], acc[i][j + 2], acc[i][j + 3]);
            if (beta) {
                float4 c = *(const float4*)cp;
                v.x += c.x; v.y += c.y; v.z += c.z; v.w += c.w;
            }
            *(float4*)cp = v;
        }
    }
}

// ---------------- persistent recurrence kernel ------------------------------
// h_t = tanh(pre[t] + h_{t-1} @ Wh); out[t] = h_t  (out doubles as h history)
// Grid: 128 blocks (<= 148 SMs -> all co-resident), each owns 8 H-columns.
// Wh strip [1024 x 8] cached in SMEM once; h_{t-1} streamed in CK-chunks with
// double-buffered cp.async.cg (L2-coherent, L1-bypass).
#define RNB 128
#define RCK 64
#define RHP 72                              // padded chunk row pitch (floats)
#define RHBUF (B_DIM * RHP)                 // 9216 floats per buffer
#define RSMEM_FLOATS (H_DIM * 8 + 2 * RHBUF)
#define RSMEM_BYTES (RSMEM_FLOATS * 4)      // 106496 bytes

__device__ __forceinline__ void cp_async16(void* sdst, const void* gsrc) {
    unsigned s = (unsigned)__cvta_generic_to_shared(sdst);
    asm volatile("cp.async.cg.shared.global [%0], [%1], 16;" :: "r"(s), "l"(gsrc));
}
__device__ __forceinline__ void cp_commit() {
    asm volatile("cp.async.commit_group;" ::: "memory");
}
template <int N>
__device__ __forceinline__ void cp_wait() {
    asm volatile("cp.async.wait_group %0;" :: "n"(N) : "memory");
}

__global__ __launch_bounds__(256, 1) void recur_kernel(
    const float* __restrict__ pre, float* __restrict__ out,
    const float* __restrict__ Wh, int steps)
{
    extern __shared__ float sm[];
    float4* ws4 = (float4*)sm;              // Wh strip as [1024][2] float4
    float* hbuf = sm + H_DIM * 8;           // 2 x [128][RHP] h chunks

    const int tid = threadIdx.x;
    const int c0 = blockIdx.x * 8;

    // Load Wh column strip once (rows k, cols c0..c0+7)
    for (int k = tid; k < H_DIM; k += 256) {
        const float4* src = (const float4*)(Wh + (size_t)k * H_DIM + c0);
        ws4[2 * k + 0] = src[0];
        ws4[2 * k + 1] = src[1];
    }
    __syncthreads();

    const int b = tid >> 1;                 // batch row 0..127
    const int cg = tid & 1;                 // column half (4 cols each)
    const int ccol = c0 + cg * 4;
    unsigned target = 0;
    volatile unsigned* vb = &g_bar;

    for (int t = 0; t < steps; t++) {
        float4 acc = make_float4(0.f, 0.f, 0.f, 0.f);
        if (t > 0) {
            const float* hprev = out + (size_t)(t - 1) * BH;
            // prologue: chunk 0 -> buffer 0
#pragma unroll
            for (int i = 0; i < 8; i++) {
                int f = i * 256 + tid;
                int bl = f >> 4, kq = f & 15;
                cp_async16(hbuf + bl * RHP + kq * 4,
                           hprev + (size_t)bl * H_DIM + kq * 4);
            }
            cp_commit();

            const int NC = H_DIM / RCK;     // 16 chunks
#pragma unroll 1
            for (int ch = 0; ch < NC; ch++) {
                int cur = ch & 1;
                if (ch + 1 < NC) {
                    float* dst = hbuf + ((ch + 1) & 1) * RHBUF;
                    int koff = (ch + 1) * RCK;
#pragma unroll
                    for (int i = 0; i < 8; i++) {
                        int f = i * 256 + tid;
                        int bl = f >> 4, kq = f & 15;
                        cp_async16(dst + bl * RHP + kq * 4,
                                   hprev + (size_t)bl * H_DIM + koff + kq * 4);
                    }
                    cp_commit();
                    cp_wait<1>();
                } else {
                    cp_wait<0>();
                }
                __syncthreads();

                const float* hb = hbuf + cur * RHBUF + b * RHP;
                const float4* wp = ws4 + ch * (RCK * 2) + cg;
#pragma unroll
                for (int k4 = 0; k4 < RCK / 4; k4++) {
                    float4 h4 = *(const float4*)(hb + k4 * 4);
                    float4 w;
                    w = wp[k4 * 8 + 0];
                    acc.x += h4.x * w.x; acc.y += h4.x * w.y;
                    acc.z += h4.x * w.z; acc.w += h4.x * w.w;
                    w = wp[k4 * 8 + 2];
                    acc.x += h4.y * w.x; acc.y += h4.y * w.y;
                    acc.z += h4.y * w.z; acc.w += h4.y * w.w;
                    w = wp[k4 * 8 + 4];
                    acc.x += h4.z * w.x; acc.y += h4.z * w.y;
                    acc.z += h4.z * w.z; acc.w += h4.z * w.w;
                    w = wp[k4 * 8 + 6];
                    acc.x += h4.w * w.x; acc.y += h4.w * w.y;
                    acc.z += h4.w * w.z; acc.w += h4.w * w.w;
                }
                __syncthreads();           // buffer reuse guard
            }
        }

        // epilogue: out[t] = tanh(pre[t] + acc)
        const float4 p4 = __ldcg((const float4*)(pre + (size_t)t * BH + b * H_DIM + ccol));
        float4 o;
        o.x = tanhf(p4.x + acc.x);
        o.y = tanhf(p4.y + acc.y);
        o.z = tanhf(p4.z + acc.z);
        o.w = tanhf(p4.w + acc.w);
        __stcg((float4*)(out + (size_t)t * BH + b * H_DIM + ccol), o);

        if (t + 1 < steps) {
            __threadfence();
            __syncthreads();
            target += RNB;
            if (tid == 0) {
                atomicAdd(&g_bar, 1u);
                while (*vb < target) __nanosleep(64);
            }
            __syncthreads();
        }
    }
}

// ---------------- launch ----------------------------------------------------
extern "C" void kernel_launch(void* const* d_in, const int* in_sizes, int n_in,
                              void* d_out, int out_size)
{
    (void)in_sizes; (void)n_in; (void)out_size;
    const float* x   = (const float*)d_in[0];
    const float* Wi0 = (const float*)d_in[1];
    const float* Wh0 = (const float*)d_in[2];
    const float* Ws0 = (const float*)d_in[3];
    const float* Wi1 = (const float*)d_in[4];
    const float* Wh1 = (const float*)d_in[5];
    const float* Ws1 = (const float*)d_in[6];
    float* out = (float*)d_out;

    void* p;
    cudaGetSymbolAddress(&p, g_pre);   float* pre = (float*)p;
    cudaGetSymbolAddress(&p, g_w0sum); float* w0s = (float*)p;
    cudaGetSymbolAddress(&p, g_sx1);   float* sx1 = (float*)p;

    cudaFuncSetAttribute(recur_kernel,
                         cudaFuncAttributeMaxDynamicSharedMemorySize, RSMEM_BYTES);

    // Layer 0 non-recurrent projection: pre0 = x @ (Wi0 + Ws0)
    k_add<<<(I_DIM * H_DIM) / 256, 256>>>(Wi0, Ws0, w0s, I_DIM * H_DIM);
    dim3 g0(H_DIM / GBN, (T_DIM * B_DIM) / GBM);
    sgemm_kernel<<<g0, 256>>>(T_DIM * B_DIM, H_DIM, I_DIM, x, w0s, pre, 0);

    // Layer 0 recurrence -> out0 in d_out[0 : T*B*H)
    k_reset_bar<<<1, 1>>>();
    recur_kernel<<<RNB, 256, RSMEM_BYTES>>>(pre, out, Wh0, T_DIM);

    // Layer 1 non-recurrent projections: pre1 = out0[1:]@Wi1 + sx1@Ws1
    int nsx = (T_DIM - 1) * B_DIM * I_DIM;
    k_sx1<<<(nsx + 255) / 256, 256>>>(x, sx1, nsx, B_DIM * I_DIM);
    dim3 g1(H_DIM / GBN, ((T_DIM - 1) * B_DIM) / GBM);
    sgemm_kernel<<<g1, 256>>>((T_DIM - 1) * B_DIM, H_DIM, H_DIM, out + BH, Wi1, pre, 0);
    sgemm_kernel<<<g1, 256>>>((T_DIM - 1) * B_DIM, H_DIM, I_DIM, sx1, Ws1, pre, 1);

    // Layer 1 recurrence -> out1 in d_out[T*B*H : (2T-1)*B*H)
    k_reset_bar<<<1, 1>>>();
    recur_kernel<<<RNB, 256, RSMEM_BYTES>>>(pre, out + (size_t)T_DIM * BH, Wh1, T_DIM - 1);
}

// round 4
// speedup vs baseline: 1.1114x; 1.1114x over previous
#include <cuda_runtime.h>
#include <cuda_bf16.h>
#include <cstdint>

// Problem constants
#define T_DIM 512
#define B_DIM 128
#define I_DIM 512
#define H_DIM 1024
#define BH (B_DIM * H_DIM)

// ---------------- scratch (static device globals: allocation-free) ----------
__device__ float g_pre[T_DIM * B_DIM * H_DIM];            // 268 MB, reused
__device__ float g_sx1[(T_DIM - 1) * B_DIM * I_DIM];      // layer-1 scaled input
__device__ unsigned g_bar;                                // grid barrier counter
// transposed + bf16-split weights: [N][K] row-major, K contiguous
__device__ __nv_bfloat16 g_w0t_hi[H_DIM * I_DIM], g_w0t_lo[H_DIM * I_DIM];
__device__ __nv_bfloat16 g_wi1t_hi[H_DIM * H_DIM], g_wi1t_lo[H_DIM * H_DIM];
__device__ __nv_bfloat16 g_ws1t_hi[H_DIM * I_DIM], g_ws1t_lo[H_DIM * I_DIM];

// ---------------- cp.async helpers -----------------------------------------
__device__ __forceinline__ void cp_async16(void* sdst, const void* gsrc) {
    unsigned s = (unsigned)__cvta_generic_to_shared(sdst);
    asm volatile("cp.async.cg.shared.global [%0], [%1], 16;" :: "r"(s), "l"(gsrc));
}
__device__ __forceinline__ void cp_commit() {
    asm volatile("cp.async.commit_group;" ::: "memory");
}
template <int N>
__device__ __forceinline__ void cp_wait() {
    asm volatile("cp.async.wait_group %0;" :: "n"(N) : "memory");
}

// ---------------- small elementwise kernels --------------------------------
__global__ void k_sx1(const float* __restrict__ x, float* __restrict__ o,
                      int n, int off) {
    int i = blockIdx.x * 256 + threadIdx.x;
    if (i < n) o[i] = 0.5f * (x[i] + x[i + off]);
}
__global__ void k_reset_bar() { g_bar = 0u; }

// transpose + bf16 hi/lo split: W[K,N] (+optional W2) -> Thi/Tlo [N,K]
__global__ void k_tsplit(const float* __restrict__ W, const float* __restrict__ W2,
                         __nv_bfloat16* __restrict__ Thi, __nv_bfloat16* __restrict__ Tlo,
                         int K, int N) {
    __shared__ float s[32][33];
    int k0 = blockIdx.x * 32, n0 = blockIdx.y * 32;
    int tx = threadIdx.x, ty = threadIdx.y;   // 32 x 8
#pragma unroll
    for (int i = 0; i < 4; i++) {
        int k = k0 + ty + i * 8;
        float v = W[(size_t)k * N + n0 + tx];
        if (W2) v += W2[(size_t)k * N + n0 + tx];
        s[ty + i * 8][tx] = v;
    }
    __syncthreads();
#pragma unroll
    for (int i = 0; i < 4; i++) {
        int n = n0 + ty + i * 8;
        float v = s[tx][ty + i * 8];
        __nv_bfloat16 h = __float2bfloat16(v);
        Thi[(size_t)n * K + k0 + tx] = h;
        Tlo[(size_t)n * K + k0 + tx] = __float2bfloat16(v - __bfloat162float(h));
    }
}

// ---------------- HMMA split-bf16 GEMM --------------------------------------
// C[M,1024] = A0[M,K0] @ B0^T (+ A1[M,K1] @ B1^T), 3-term bf16 split, f32 accum.
// A fp32 row-major (K contiguous); B pre-split bf16 [N,K] row-major.
// Block: 128x128x32, 256 threads = 8 warps as 2(m) x 4(n), warp tile 64x32.
#define PITCH 40                            // bf16 elems per smem row (80 B)
#define TILE_HL (128 * PITCH)               // one [128][40] bf16 matrix
#define SM_A 0
#define SM_B (4 * TILE_HL)                  // after A's [2 buf][2 hl]
#define SM_TOTAL_BF16 (8 * TILE_HL)         // 40960 bf16 = 81920 B

__device__ __forceinline__ void mma_bf16(float* c, const uint32_t* a, const uint32_t* b) {
    asm volatile(
        "mma.sync.aligned.m16n8k16.row.col.f32.bf16.bf16.f32 "
        "{%0,%1,%2,%3}, {%4,%5,%6,%7}, {%8,%9}, {%0,%1,%2,%3};"
        : "+f"(c[0]), "+f"(c[1]), "+f"(c[2]), "+f"(c[3])
        : "r"(a[0]), "r"(a[1]), "r"(a[2]), "r"(a[3]), "r"(b[0]), "r"(b[1]));
}

__global__ __launch_bounds__(256) void tc_gemm(
    float* __restrict__ C,
    const float* __restrict__ A0, int K0,
    const __nv_bfloat16* __restrict__ B0hi, const __nv_bfloat16* __restrict__ B0lo,
    const float* __restrict__ A1, int K1,
    const __nv_bfloat16* __restrict__ B1hi, const __nv_bfloat16* __restrict__ B1lo)
{
    extern __shared__ __align__(16) __nv_bfloat16 sm[];
    const int tid = threadIdx.x;
    const int wid = tid >> 5, lane = tid & 31;
    const int g = lane >> 2, tg = lane & 3;
    const int wm = (wid >> 2) * 64, wn = (wid & 3) * 32;
    const int mrow0 = blockIdx.y * 128;
    const int ncol0 = blockIdx.x * 128;

    const int NI0 = K0 / 32;
    const int NI = NI0 + K1 / 32;

    float acc[4][4][4];
#pragma unroll
    for (int i = 0; i < 4; i++)
#pragma unroll
        for (int j = 0; j < 4; j++)
#pragma unroll
            for (int q = 0; q < 4; q++) acc[i][j][q] = 0.f;

    // A-fill thread mapping: row = tid>>1 (2 threads/row), 16 floats each
    const int ar = tid >> 1, ah = (tid & 1) * 16;
    // B-fill mapping: hl = tid>>7, row = tid&127, 4 x 16B chunks
    const int bhl = tid >> 7, br = tid & 127;

    // helper lambdas as macros
#define A_SRC(A, K, koff) ((const float4*)((A) + (size_t)(mrow0 + ar) * (K) + (koff) + ah))
#define STS_A(buf, st)                                                                 \
    {                                                                                  \
        __nv_bfloat16* dh = sm + SM_A + ((buf) * 2 + 0) * TILE_HL + ar * PITCH + ah;   \
        __nv_bfloat16* dl = sm + SM_A + ((buf) * 2 + 1) * TILE_HL + ar * PITCH + ah;   \
        _Pragma("unroll")                                                              \
        for (int q = 0; q < 4; q++) {                                                  \
            float f[4] = {st[q].x, st[q].y, st[q].z, st[q].w};                         \
            uint32_t hi2[2], lo2[2];                                                   \
            _Pragma("unroll")                                                          \
            for (int j = 0; j < 2; j++) {                                              \
                __nv_bfloat16 h0 = __float2bfloat16(f[2 * j]);                         \
                __nv_bfloat16 h1 = __float2bfloat16(f[2 * j + 1]);                     \
                __nv_bfloat16 l0 = __float2bfloat16(f[2 * j] - __bfloat162float(h0));  \
                __nv_bfloat16 l1 = __float2bfloat16(f[2 * j + 1] - __bfloat162float(h1)); \
                hi2[j] = (uint32_t)__bfloat16_as_ushort(h0) |                          \
                         ((uint32_t)__bfloat16_as_ushort(h1) << 16);                   \
                lo2[j] = (uint32_t)__bfloat16_as_ushort(l0) |                          \
                         ((uint32_t)__bfloat16_as_ushort(l1) << 16);                   \
            }                                                                          \
            *(uint2*)(dh + q * 4) = make_uint2(hi2[0], hi2[1]);                        \
            *(uint2*)(dl + q * 4) = make_uint2(lo2[0], lo2[1]);                        \
        }                                                                              \
    }
#define LOAD_B(buf, Bhi, Blo, K, koff)                                                 \
    {                                                                                  \
        const __nv_bfloat16* src = ((bhl) ? (Blo) : (Bhi)) +                           \
                                   (size_t)(ncol0 + br) * (K) + (koff);                \
        __nv_bfloat16* dst = sm + SM_B + ((buf) * 2 + bhl) * TILE_HL + br * PITCH;     \
        _Pragma("unroll")                                                              \
        for (int q = 0; q < 4; q++) cp_async16(dst + q * 8, src + q * 8);              \
    }

    // prologue: fill iter 0 into buf 0
    {
        float4 st[4];
        const float4* s4 = A_SRC(A0, K0, 0);
#pragma unroll
        for (int q = 0; q < 4; q++) st[q] = s4[q];
        STS_A(0, st);
        LOAD_B(0, B0hi, B0lo, K0, 0);
        cp_commit();
    }

    for (int i = 0; i < NI; i++) {
        cp_wait<0>();
        __syncthreads();

        const int buf = i & 1;
        float4 st[4];
        bool have_next = (i + 1 < NI);
        if (have_next) {
            int ni = i + 1;
            if (ni < NI0) {
                const float4* s4 = A_SRC(A0, K0, ni * 32);
#pragma unroll
                for (int q = 0; q < 4; q++) st[q] = s4[q];
                LOAD_B(buf ^ 1, B0hi, B0lo, K0, ni * 32);
            } else {
                int koff = (ni - NI0) * 32;
                const float4* s4 = A_SRC(A1, K1, koff);
#pragma unroll
                for (int q = 0; q < 4; q++) st[q] = s4[q];
                LOAD_B(buf ^ 1, B1hi, B1lo, K1, koff);
            }
            cp_commit();
        }

        // ---- compute on buf ----
        const __nv_bfloat16* sAh = sm + SM_A + (buf * 2 + 0) * TILE_HL;
        const __nv_bfloat16* sAl = sm + SM_A + (buf * 2 + 1) * TILE_HL;
        const __nv_bfloat16* sBh = sm + SM_B + (buf * 2 + 0) * TILE_HL;
        const __nv_bfloat16* sBl = sm + SM_B + (buf * 2 + 1) * TILE_HL;
#pragma unroll
        for (int kk = 0; kk < 32; kk += 16) {
            uint32_t bh[4][2], bl[4][2];
#pragma unroll
            for (int nt = 0; nt < 4; nt++) {
                int n = wn + nt * 8 + g;
                bh[nt][0] = *(const uint32_t*)(sBh + n * PITCH + kk + tg * 2);
                bh[nt][1] = *(const uint32_t*)(sBh + n * PITCH + kk + tg * 2 + 8);
                bl[nt][0] = *(const uint32_t*)(sBl + n * PITCH + kk + tg * 2);
                bl[nt][1] = *(const uint32_t*)(sBl + n * PITCH + kk + tg * 2 + 8);
            }
#pragma unroll
            for (int mt = 0; mt < 4; mt++) {
                int r = wm + mt * 16 + g;
                uint32_t a_hi[4], a_lo[4];
                a_hi[0] = *(const uint32_t*)(sAh + r * PITCH + kk + tg * 2);
                a_hi[1] = *(const uint32_t*)(sAh + (r + 8) * PITCH + kk + tg * 2);
                a_hi[2] = *(const uint32_t*)(sAh + r * PITCH + kk + tg * 2 + 8);
                a_hi[3] = *(const uint32_t*)(sAh + (r + 8) * PITCH + kk + tg * 2 + 8);
                a_lo[0] = *(const uint32_t*)(sAl + r * PITCH + kk + tg * 2);
                a_lo[1] = *(const uint32_t*)(sAl + (r + 8) * PITCH + kk + tg * 2);
                a_lo[2] = *(const uint32_t*)(sAl + r * PITCH + kk + tg * 2 + 8);
                a_lo[3] = *(const uint32_t*)(sAl + (r + 8) * PITCH + kk + tg * 2 + 8);
#pragma unroll
                for (int nt = 0; nt < 4; nt++) {
                    mma_bf16(acc[mt][nt], a_hi, bh[nt]);
                    mma_bf16(acc[mt][nt], a_lo, bh[nt]);
                    mma_bf16(acc[mt][nt], a_hi, bl[nt]);
                }
            }
        }

        if (have_next) STS_A(buf ^ 1, st);
    }

    // ---- epilogue ----
#pragma unroll
    for (int mt = 0; mt < 4; mt++) {
#pragma unroll
        for (int nt = 0; nt < 4; nt++) {
            int r0 = mrow0 + wm + mt * 16 + g;
            int c0 = ncol0 + wn + nt * 8 + tg * 2;
            *(float2*)(C + (size_t)r0 * 1024 + c0) =
                make_float2(acc[mt][nt][0], acc[mt][nt][1]);
            *(float2*)(C + (size_t)(r0 + 8) * 1024 + c0) =
                make_float2(acc[mt][nt][2], acc[mt][nt][3]);
        }
    }
#undef A_SRC
#undef STS_A
#undef LOAD_B
}

// ---------------- persistent recurrence kernel (unchanged, known-good) ------
#define RNB 128
#define RCK 64
#define RHP 72
#define RHBUF (B_DIM * RHP)
#define RSMEM_FLOATS (H_DIM * 8 + 2 * RHBUF)
#define RSMEM_BYTES (RSMEM_FLOATS * 4)

__global__ __launch_bounds__(256, 1) void recur_kernel(
    const float* __restrict__ pre, float* __restrict__ out,
    const float* __restrict__ Wh, int steps)
{
    extern __shared__ float smf[];
    float4* ws4 = (float4*)smf;
    float* hbuf = smf + H_DIM * 8;

    const int tid = threadIdx.x;
    const int c0 = blockIdx.x * 8;

    for (int k = tid; k < H_DIM; k += 256) {
        const float4* src = (const float4*)(Wh + (size_t)k * H_DIM + c0);
        ws4[2 * k + 0] = src[0];
        ws4[2 * k + 1] = src[1];
    }
    __syncthreads();

    const int b = tid >> 1;
    const int cg = tid & 1;
    const int ccol = c0 + cg * 4;
    unsigned target = 0;
    volatile unsigned* vb = &g_bar;

    for (int t = 0; t < steps; t++) {
        float4 acc = make_float4(0.f, 0.f, 0.f, 0.f);
        if (t > 0) {
            const float* hprev = out + (size_t)(t - 1) * BH;
#pragma unroll
            for (int i = 0; i < 8; i++) {
                int f = i * 256 + tid;
                int bl = f >> 4, kq = f & 15;
                cp_async16(hbuf + bl * RHP + kq * 4,
                           hprev + (size_t)bl * H_DIM + kq * 4);
            }
            cp_commit();

            const int NCh = H_DIM / RCK;
#pragma unroll 1
            for (int ch = 0; ch < NCh; ch++) {
                int cur = ch & 1;
                if (ch + 1 < NCh) {
                    float* dst = hbuf + ((ch + 1) & 1) * RHBUF;
                    int koff = (ch + 1) * RCK;
#pragma unroll
                    for (int i = 0; i < 8; i++) {
                        int f = i * 256 + tid;
                        int bl = f >> 4, kq = f & 15;
                        cp_async16(dst + bl * RHP + kq * 4,
                                   hprev + (size_t)bl * H_DIM + koff + kq * 4);
                    }
                    cp_commit();
                    cp_wait<1>();
                } else {
                    cp_wait<0>();
                }
                __syncthreads();

                const float* hb = hbuf + cur * RHBUF + b * RHP;
                const float4* wp = ws4 + ch * (RCK * 2) + cg;
#pragma unroll
                for (int k4 = 0; k4 < RCK / 4; k4++) {
                    float4 h4 = *(const float4*)(hb + k4 * 4);
                    float4 w;
                    w = wp[k4 * 8 + 0];
                    acc.x += h4.x * w.x; acc.y += h4.x * w.y;
                    acc.z += h4.x * w.z; acc.w += h4.x * w.w;
                    w = wp[k4 * 8 + 2];
                    acc.x += h4.y * w.x; acc.y += h4.y * w.y;
                    acc.z += h4.y * w.z; acc.w += h4.y * w.w;
                    w = wp[k4 * 8 + 4];
                    acc.x += h4.z * w.x; acc.y += h4.z * w.y;
                    acc.z += h4.z * w.z; acc.w += h4.z * w.w;
                    w = wp[k4 * 8 + 6];
                    acc.x += h4.w * w.x; acc.y += h4.w * w.y;
                    acc.z += h4.w * w.z; acc.w += h4.w * w.w;
                }
                __syncthreads();
            }
        }

        const float4 p4 = __ldcg((const float4*)(pre + (size_t)t * BH + b * H_DIM + ccol));
        float4 o;
        o.x = tanhf(p4.x + acc.x);
        o.y = tanhf(p4.y + acc.y);
        o.z = tanhf(p4.z + acc.z);
        o.w = tanhf(p4.w + acc.w);
        __stcg((float4*)(out + (size_t)t * BH + b * H_DIM + ccol), o);

        if (t + 1 < steps) {
            __threadfence();
            __syncthreads();
            target += RNB;
            if (tid == 0) {
                atomicAdd(&g_bar, 1u);
                while (*vb < target) __nanosleep(64);
            }
            __syncthreads();
        }
    }
}

// ---------------- launch ----------------------------------------------------
extern "C" void kernel_launch(void* const* d_in, const int* in_sizes, int n_in,
                              void* d_out, int out_size)
{
    (void)in_sizes; (void)n_in; (void)out_size;
    const float* x   = (const float*)d_in[0];
    const float* Wi0 = (const float*)d_in[1];
    const float* Wh0 = (const float*)d_in[2];
    const float* Ws0 = (const float*)d_in[3];
    const float* Wi1 = (const float*)d_in[4];
    const float* Wh1 = (const float*)d_in[5];
    const float* Ws1 = (const float*)d_in[6];
    float* out = (float*)d_out;

    void* p;
    cudaGetSymbolAddress(&p, g_pre);     float* pre = (float*)p;
    cudaGetSymbolAddress(&p, g_sx1);     float* sx1 = (float*)p;
    cudaGetSymbolAddress(&p, g_w0t_hi);  __nv_bfloat16* w0hi = (__nv_bfloat16*)p;
    cudaGetSymbolAddress(&p, g_w0t_lo);  __nv_bfloat16* w0lo = (__nv_bfloat16*)p;
    cudaGetSymbolAddress(&p, g_wi1t_hi); __nv_bfloat16* wi1hi = (__nv_bfloat16*)p;
    cudaGetSymbolAddress(&p, g_wi1t_lo); __nv_bfloat16* wi1lo = (__nv_bfloat16*)p;
    cudaGetSymbolAddress(&p, g_ws1t_hi); __nv_bfloat16* ws1hi = (__nv_bfloat16*)p;
    cudaGetSymbolAddress(&p, g_ws1t_lo); __nv_bfloat16* ws1lo = (__nv_bfloat16*)p;

    cudaFuncSetAttribute(recur_kernel,
                         cudaFuncAttributeMaxDynamicSharedMemorySize, RSMEM_BYTES);
    cudaFuncSetAttribute(tc_gemm,
                         cudaFuncAttributeMaxDynamicSharedMemorySize,
                         SM_TOTAL_BF16 * 2);

    // weight prep: transpose + bf16 hi/lo split
    dim3 tb(32, 8);
    k_tsplit<<<dim3(I_DIM / 32, H_DIM / 32), tb>>>(Wi0, Ws0, w0hi, w0lo, I_DIM, H_DIM);
    k_tsplit<<<dim3(H_DIM / 32, H_DIM / 32), tb>>>(Wi1, nullptr, wi1hi, wi1lo, H_DIM, H_DIM);
    k_tsplit<<<dim3(I_DIM / 32, H_DIM / 32), tb>>>(Ws1, nullptr, ws1hi, ws1lo, I_DIM, H_DIM);

    // layer 0: pre0 = x @ (Wi0+Ws0)   [HMMA split-bf16]
    tc_gemm<<<dim3(H_DIM / 128, (T_DIM * B_DIM) / 128), 256, SM_TOTAL_BF16 * 2>>>(
        pre, x, I_DIM, w0hi, w0lo, nullptr, 0, nullptr, nullptr);

    k_reset_bar<<<1, 1>>>();
    recur_kernel<<<RNB, 256, RSMEM_BYTES>>>(pre, out, Wh0, T_DIM);

    // layer 1: pre1 = out0[1:] @ Wi1 + sx1 @ Ws1  (fused, register-accumulated)
    int nsx = (T_DIM - 1) * B_DIM * I_DIM;
    k_sx1<<<(nsx + 255) / 256, 256>>>(x, sx1, nsx, B_DIM * I_DIM);
    tc_gemm<<<dim3(H_DIM / 128, ((T_DIM - 1) * B_DIM) / 128), 256, SM_TOTAL_BF16 * 2>>>(
        pre, out + BH, H_DIM, wi1hi, wi1lo, sx1, I_DIM, ws1hi, ws1lo);

    k_reset_bar<<<1, 1>>>();
    recur_kernel<<<RNB, 256, RSMEM_BYTES>>>(pre, out + (size_t)T_DIM * BH, Wh1, T_DIM - 1);
}

// round 6
// speedup vs baseline: 2.3161x; 2.0839x over previous
#include <cuda_runtime.h>
#include <cuda_bf16.h>
#include <cstdint>

// Problem constants
#define T_DIM 512
#define B_DIM 128
#define I_DIM 512
#define H_DIM 1024
#define BH (B_DIM * H_DIM)

// ---------------- scratch (static device globals: allocation-free) ----------
__device__ float g_pre[T_DIM * B_DIM * H_DIM];            // 268 MB, reused
__device__ float g_sx1[(T_DIM - 1) * B_DIM * I_DIM];      // layer-1 scaled input
__device__ unsigned g_bar;                                // grid barrier counter
// h state as pre-split bf16, double-buffered across steps
__device__ __nv_bfloat16 g_hhi[2 * BH], g_hlo[2 * BH];
// transposed + bf16-split weights: [N][K] row-major, K contiguous
__device__ __nv_bfloat16 g_w0t_hi[H_DIM * I_DIM], g_w0t_lo[H_DIM * I_DIM];
__device__ __nv_bfloat16 g_wi1t_hi[H_DIM * H_DIM], g_wi1t_lo[H_DIM * H_DIM];
__device__ __nv_bfloat16 g_ws1t_hi[H_DIM * I_DIM], g_ws1t_lo[H_DIM * I_DIM];

// ---------------- cp.async helpers -----------------------------------------
__device__ __forceinline__ void cp_async16(void* sdst, const void* gsrc) {
    unsigned s = (unsigned)__cvta_generic_to_shared(sdst);
    asm volatile("cp.async.cg.shared.global [%0], [%1], 16;" :: "r"(s), "l"(gsrc));
}
__device__ __forceinline__ void cp_commit() {
    asm volatile("cp.async.commit_group;" ::: "memory");
}
template <int N>
__device__ __forceinline__ void cp_wait() {
    asm volatile("cp.async.wait_group %0;" :: "n"(N) : "memory");
}

__device__ __forceinline__ void mma_bf16(float* c, const uint32_t* a, const uint32_t* b) {
    asm volatile(
        "mma.sync.aligned.m16n8k16.row.col.f32.bf16.bf16.f32 "
        "{%0,%1,%2,%3}, {%4,%5,%6,%7}, {%8,%9}, {%0,%1,%2,%3};"
        : "+f"(c[0]), "+f"(c[1]), "+f"(c[2]), "+f"(c[3])
        : "r"(a[0]), "r"(a[1]), "r"(a[2]), "r"(a[3]), "r"(b[0]), "r"(b[1]));
}

// ---------------- small elementwise kernels --------------------------------
__global__ void k_sx1(const float* __restrict__ x, float* __restrict__ o,
                      int n, int off) {
    int i = blockIdx.x * 256 + threadIdx.x;
    if (i < n) o[i] = 0.5f * (x[i] + x[i + off]);
}
__global__ void k_reset_bar() { g_bar = 0u; }

// transpose + bf16 hi/lo split: W[K,N] (+optional W2) -> Thi/Tlo [N,K]
__global__ void k_tsplit(const float* __restrict__ W, const float* __restrict__ W2,
                         __nv_bfloat16* __restrict__ Thi, __nv_bfloat16* __restrict__ Tlo,
                         int K, int N) {
    __shared__ float s[32][33];
    int k0 = blockIdx.x * 32, n0 = blockIdx.y * 32;
    int tx = threadIdx.x, ty = threadIdx.y;   // 32 x 8
#pragma unroll
    for (int i = 0; i < 4; i++) {
        int k = k0 + ty + i * 8;
        float v = W[(size_t)k * N + n0 + tx];
        if (W2) v += W2[(size_t)k * N + n0 + tx];
        s[ty + i * 8][tx] = v;
    }
    __syncthreads();
#pragma unroll
    for (int i = 0; i < 4; i++) {
        int n = n0 + ty + i * 8;
        float v = s[tx][ty + i * 8];
        __nv_bfloat16 h = __float2bfloat16(v);
        Thi[(size_t)n * K + k0 + tx] = h;
        Tlo[(size_t)n * K + k0 + tx] = __float2bfloat16(v - __bfloat162float(h));
    }
}

// ---------------- HMMA split-bf16 GEMM (unchanged, proven R4) ---------------
#define PITCH 40
#define TILE_HL (128 * PITCH)
#define SM_A 0
#define SM_B (4 * TILE_HL)
#define SM_TOTAL_BF16 (8 * TILE_HL)

__global__ __launch_bounds__(256) void tc_gemm(
    float* __restrict__ C,
    const float* __restrict__ A0, int K0,
    const __nv_bfloat16* __restrict__ B0hi, const __nv_bfloat16* __restrict__ B0lo,
    const float* __restrict__ A1, int K1,
    const __nv_bfloat16* __restrict__ B1hi, const __nv_bfloat16* __restrict__ B1lo)
{
    extern __shared__ __align__(16) __nv_bfloat16 sm[];
    const int tid = threadIdx.x;
    const int wid = tid >> 5, lane = tid & 31;
    const int g = lane >> 2, tg = lane & 3;
    const int wm = (wid >> 2) * 64, wn = (wid & 3) * 32;
    const int mrow0 = blockIdx.y * 128;
    const int ncol0 = blockIdx.x * 128;

    const int NI0 = K0 / 32;
    const int NI = NI0 + K1 / 32;

    float acc[4][4][4];
#pragma unroll
    for (int i = 0; i < 4; i++)
#pragma unroll
        for (int j = 0; j < 4; j++)
#pragma unroll
            for (int q = 0; q < 4; q++) acc[i][j][q] = 0.f;

    const int ar = tid >> 1, ah = (tid & 1) * 16;
    const int bhl = tid >> 7, br = tid & 127;

#define A_SRC(A, K, koff) ((const float4*)((A) + (size_t)(mrow0 + ar) * (K) + (koff) + ah))
#define STS_A(buf, st)                                                                 \
    {                                                                                  \
        __nv_bfloat16* dh = sm + SM_A + ((buf) * 2 + 0) * TILE_HL + ar * PITCH + ah;   \
        __nv_bfloat16* dl = sm + SM_A + ((buf) * 2 + 1) * TILE_HL + ar * PITCH + ah;   \
        _Pragma("unroll")                                                              \
        for (int q = 0; q < 4; q++) {                                                  \
            float f[4] = {st[q].x, st[q].y, st[q].z, st[q].w};                         \
            uint32_t hi2[2], lo2[2];                                                   \
            _Pragma("unroll")                                                          \
            for (int j = 0; j < 2; j++) {                                              \
                __nv_bfloat16 h0 = __float2bfloat16(f[2 * j]);                         \
                __nv_bfloat16 h1 = __float2bfloat16(f[2 * j + 1]);                     \
                __nv_bfloat16 l0 = __float2bfloat16(f[2 * j] - __bfloat162float(h0));  \
                __nv_bfloat16 l1 = __float2bfloat16(f[2 * j + 1] - __bfloat162float(h1)); \
                hi2[j] = (uint32_t)__bfloat16_as_ushort(h0) |                          \
                         ((uint32_t)__bfloat16_as_ushort(h1) << 16);                   \
                lo2[j] = (uint32_t)__bfloat16_as_ushort(l0) |                          \
                         ((uint32_t)__bfloat16_as_ushort(l1) << 16);                   \
            }                                                                          \
            *(uint2*)(dh + q * 4) = make_uint2(hi2[0], hi2[1]);                        \
            *(uint2*)(dl + q * 4) = make_uint2(lo2[0], lo2[1]);                        \
        }                                                                              \
    }
#define LOAD_B(buf, Bhi, Blo, K, koff)                                                 \
    {                                                                                  \
        const __nv_bfloat16* src = ((bhl) ? (Blo) : (Bhi)) +                           \
                                   (size_t)(ncol0 + br) * (K) + (koff);                \
        __nv_bfloat16* dst = sm + SM_B + ((buf) * 2 + bhl) * TILE_HL + br * PITCH;     \
        _Pragma("unroll")                                                              \
        for (int q = 0; q < 4; q++) cp_async16(dst + q * 8, src + q * 8);              \
    }

    {
        float4 st[4];
        const float4* s4 = A_SRC(A0, K0, 0);
#pragma unroll
        for (int q = 0; q < 4; q++) st[q] = s4[q];
        STS_A(0, st);
        LOAD_B(0, B0hi, B0lo, K0, 0);
        cp_commit();
    }

    for (int i = 0; i < NI; i++) {
        cp_wait<0>();
        __syncthreads();

        const int buf = i & 1;
        float4 st[4];
        bool have_next = (i + 1 < NI);
        if (have_next) {
            int ni = i + 1;
            if (ni < NI0) {
                const float4* s4 = A_SRC(A0, K0, ni * 32);
#pragma unroll
                for (int q = 0; q < 4; q++) st[q] = s4[q];
                LOAD_B(buf ^ 1, B0hi, B0lo, K0, ni * 32);
            } else {
                int koff = (ni - NI0) * 32;
                const float4* s4 = A_SRC(A1, K1, koff);
#pragma unroll
                for (int q = 0; q < 4; q++) st[q] = s4[q];
                LOAD_B(buf ^ 1, B1hi, B1lo, K1, koff);
            }
            cp_commit();
        }

        const __nv_bfloat16* sAh = sm + SM_A + (buf * 2 + 0) * TILE_HL;
        const __nv_bfloat16* sAl = sm + SM_A + (buf * 2 + 1) * TILE_HL;
        const __nv_bfloat16* sBh = sm + SM_B + (buf * 2 + 0) * TILE_HL;
        const __nv_bfloat16* sBl = sm + SM_B + (buf * 2 + 1) * TILE_HL;
#pragma unroll
        for (int kk = 0; kk < 32; kk += 16) {
            uint32_t bh[4][2], bl[4][2];
#pragma unroll
            for (int nt = 0; nt < 4; nt++) {
                int n = wn + nt * 8 + g;
                bh[nt][0] = *(const uint32_t*)(sBh + n * PITCH + kk + tg * 2);
                bh[nt][1] = *(const uint32_t*)(sBh + n * PITCH + kk + tg * 2 + 8);
                bl[nt][0] = *(const uint32_t*)(sBl + n * PITCH + kk + tg * 2);
                bl[nt][1] = *(const uint32_t*)(sBl + n * PITCH + kk + tg * 2 + 8);
            }
#pragma unroll
            for (int mt = 0; mt < 4; mt++) {
                int r = wm + mt * 16 + g;
                uint32_t a_hi[4], a_lo[4];
                a_hi[0] = *(const uint32_t*)(sAh + r * PITCH + kk + tg * 2);
                a_hi[1] = *(const uint32_t*)(sAh + (r + 8) * PITCH + kk + tg * 2);
                a_hi[2] = *(const uint32_t*)(sAh + r * PITCH + kk + tg * 2 + 8);
                a_hi[3] = *(const uint32_t*)(sAh + (r + 8) * PITCH + kk + tg * 2 + 8);
                a_lo[0] = *(const uint32_t*)(sAl + r * PITCH + kk + tg * 2);
                a_lo[1] = *(const uint32_t*)(sAl + (r + 8) * PITCH + kk + tg * 2);
                a_lo[2] = *(const uint32_t*)(sAl + r * PITCH + kk + tg * 2 + 8);
                a_lo[3] = *(const uint32_t*)(sAl + (r + 8) * PITCH + kk + tg * 2 + 8);
#pragma unroll
                for (int nt = 0; nt < 4; nt++) {
                    mma_bf16(acc[mt][nt], a_hi, bh[nt]);
                    mma_bf16(acc[mt][nt], a_lo, bh[nt]);
                    mma_bf16(acc[mt][nt], a_hi, bl[nt]);
                }
            }
        }

        if (have_next) STS_A(buf ^ 1, st);
    }

#pragma unroll
    for (int mt = 0; mt < 4; mt++) {
#pragma unroll
        for (int nt = 0; nt < 4; nt++) {
            int r0 = mrow0 + wm + mt * 16 + g;
            int c0 = ncol0 + wn + nt * 8 + tg * 2;
            *(float2*)(C + (size_t)r0 * 1024 + c0) =
                make_float2(acc[mt][nt][0], acc[mt][nt][1]);
            *(float2*)(C + (size_t)(r0 + 8) * 1024 + c0) =
                make_float2(acc[mt][nt][2], acc[mt][nt][3]);
        }
    }
#undef A_SRC
#undef STS_A
#undef LOAD_B
}

// ---------------- HMMA persistent recurrence --------------------------------
// h_t = tanh(pre[t] + h_{t-1} @ Wh). 128 blocks, each owns a 32x32 output tile
// (rowgroup = bid>>5, colgroup = bid&31). Wh strip (32 cols, K=1024, hi+lo bf16)
// resident in SMEM for all steps. h_{t-1} read as pre-split bf16 hi/lo from
// global (double-buffered by step parity), streamed in 4 chunks of K=256 via
// double-buffered cp.async. 8 warps = 2m x 2n x 2k-split; cross-warp K-reduce
// through SMEM each step; epilogue writes fp32 out + split-bf16 h for t+1.
#define WP 1032                         // weight K pitch (bf16 elems)
#define HP 264                          // h chunk K pitch (bf16 elems)
#define SW_ELEMS (32 * WP)              // 33024
#define HB_ELEMS (32 * HP)              // 8448
#define SM2_H_OFF (2 * SW_ELEMS)        // bf16 offset of h chunk buffers
#define SM2_RED_OFF ((2 * SW_ELEMS + 4 * HB_ELEMS) * 2)   // 199680 bytes
#define SM2_BYTES (SM2_RED_OFF + 4096)  // 203776 bytes

__global__ __launch_bounds__(256, 1) void recur2(
    const float* __restrict__ pre, float* __restrict__ out,
    const float* __restrict__ Wh,
    __nv_bfloat16* __restrict__ hhi, __nv_bfloat16* __restrict__ hlo,
    int steps)
{
    extern __shared__ __align__(16) __nv_bfloat16 sm2[];
    float* red = (float*)((char*)sm2 + SM2_RED_OFF);
    const int tid = threadIdx.x, wid = tid >> 5, lane = tid & 31;
    const int g = lane >> 2, tg = lane & 3;
    const int kg = wid >> 2;                 // K-split half
    const int wm = ((wid >> 1) & 1) * 16;    // m-half within 32 rows
    const int wn = (wid & 1) * 16;           // n-half within 32 cols
    const int r0 = (blockIdx.x >> 5) * 32;
    const int c0 = (blockIdx.x & 31) * 32;

    // ---- load + split Wh strip into SMEM once ----
    for (int k = wid; k < H_DIM; k += 8) {
        float w = Wh[(size_t)k * H_DIM + c0 + lane];
        __nv_bfloat16 h = __float2bfloat16(w);
        sm2[lane * WP + k] = h;
        sm2[SW_ELEMS + lane * WP + k] = __float2bfloat16(w - __bfloat162float(h));
    }
    __syncthreads();

    unsigned target = 0;
    volatile unsigned* vb = &g_bar;

#define ISSUE(c, hp)                                                                     \
    {                                                                                    \
        _Pragma("unroll")                                                                \
        for (int i = 0; i < 8; i++) {                                                    \
            int f = i * 256 + tid;                                                       \
            int hl = f >> 10, rem = f & 1023;                                            \
            int row = rem >> 5, seg = rem & 31;                                          \
            const __nv_bfloat16* src = (hl ? hlo : hhi) + (size_t)(hp)*BH +              \
                                       (size_t)(r0 + row) * H_DIM + (c)*256 + seg * 8;   \
            cp_async16(sm2 + SM2_H_OFF + (((c)&1) * 2 + hl) * HB_ELEMS + row * HP +      \
                           seg * 8, src);                                                \
        }                                                                                \
        cp_commit();                                                                     \
    }

    for (int t = 0; t < steps; t++) {
        float acc[2][4];
#pragma unroll
        for (int nt = 0; nt < 2; nt++)
#pragma unroll
            for (int q = 0; q < 4; q++) acc[nt][q] = 0.f;

        if (t > 0) {
            const int hp = (t - 1) & 1;
            ISSUE(0, hp);
            ISSUE(1, hp);
#pragma unroll 1
            for (int c = 0; c < 4; c++) {
                if (c < 3) cp_wait<1>(); else cp_wait<0>();
                __syncthreads();
                if (kg == (c >> 1)) {
                    const __nv_bfloat16* sAh = sm2 + SM2_H_OFF + ((c & 1) * 2) * HB_ELEMS;
                    const __nv_bfloat16* sAl = sAh + HB_ELEMS;
                    const __nv_bfloat16* sBh = sm2;
                    const __nv_bfloat16* sBl = sm2 + SW_ELEMS;
#pragma unroll 4
                    for (int kt = 0; kt < 16; kt++) {
                        const int kk = kt * 16;
                        const int kgl = c * 256 + kk;
                        const int rlo = (wm + g) * HP + kk + tg * 2;
                        const int rhi = (wm + g + 8) * HP + kk + tg * 2;
                        uint32_t ahf[4], alf[4];
                        ahf[0] = *(const uint32_t*)(sAh + rlo);
                        ahf[1] = *(const uint32_t*)(sAh + rhi);
                        ahf[2] = *(const uint32_t*)(sAh + rlo + 8);
                        ahf[3] = *(const uint32_t*)(sAh + rhi + 8);
                        alf[0] = *(const uint32_t*)(sAl + rlo);
                        alf[1] = *(const uint32_t*)(sAl + rhi);
                        alf[2] = *(const uint32_t*)(sAl + rlo + 8);
                        alf[3] = *(const uint32_t*)(sAl + rhi + 8);
#pragma unroll
                        for (int nt = 0; nt < 2; nt++) {
                            const int nb = (wn + nt * 8 + g) * WP + kgl + tg * 2;
                            uint32_t bhf[2], blf[2];
                            bhf[0] = *(const uint32_t*)(sm2 + nb);
                            bhf[1] = *(const uint32_t*)(sm2 + nb + 8);
                            blf[0] = *(const uint32_t*)(sBl + nb);
                            blf[1] = *(const uint32_t*)(sBl + nb + 8);
                            (void)sBh;
                            mma_bf16(acc[nt], ahf, bhf);
                            mma_bf16(acc[nt], alf, bhf);
                            mma_bf16(acc[nt], ahf, blf);
                        }
                    }
                }
                __syncthreads();
                if (c + 2 < 4) ISSUE(c + 2, hp);
            }
        }

        // ---- cross-warp K reduction + epilogue ----
        if (kg) {
            float* rp = red + ((wid & 3) * 32 + lane) * 8;
            *(float4*)rp = make_float4(acc[0][0], acc[0][1], acc[0][2], acc[0][3]);
            *(float4*)(rp + 4) = make_float4(acc[1][0], acc[1][1], acc[1][2], acc[1][3]);
        }
        __syncthreads();
        if (!kg) {
            const float* rp = red + ((wid & 3) * 32 + lane) * 8;
            float4 o0 = *(const float4*)rp;
            float4 o1 = *(const float4*)(rp + 4);
            acc[0][0] += o0.x; acc[0][1] += o0.y; acc[0][2] += o0.z; acc[0][3] += o0.w;
            acc[1][0] += o1.x; acc[1][1] += o1.y; acc[1][2] += o1.z; acc[1][3] += o1.w;

            const int rlo = r0 + wm + g, rhi2 = rlo + 8;
            const int hcur = t & 1;
            const float* pb = pre + (size_t)t * BH;
            float* ob = out + (size_t)t * BH;
#pragma unroll
            for (int nt = 0; nt < 2; nt++) {
                const int col = c0 + wn + nt * 8 + tg * 2;
                float2 plo = *(const float2*)(pb + (size_t)rlo * H_DIM + col);
                float2 phi = *(const float2*)(pb + (size_t)rhi2 * H_DIM + col);
                float v0 = tanhf(plo.x + acc[nt][0]);
                float v1 = tanhf(plo.y + acc[nt][1]);
                float v2 = tanhf(phi.x + acc[nt][2]);
                float v3 = tanhf(phi.y + acc[nt][3]);
                *(float2*)(ob + (size_t)rlo * H_DIM + col) = make_float2(v0, v1);
                *(float2*)(ob + (size_t)rhi2 * H_DIM + col) = make_float2(v2, v3);
                // split-bf16 stores for next step's consumption
                __nv_bfloat16 h0 = __float2bfloat16(v0), h1 = __float2bfloat16(v1);
                __nv_bfloat16 h2 = __float2bfloat16(v2), h3 = __float2bfloat16(v3);
                __nv_bfloat16 l0 = __float2bfloat16(v0 - __bfloat162float(h0));
                __nv_bfloat16 l1 = __float2bfloat16(v1 - __bfloat162float(h1));
                __nv_bfloat16 l2 = __float2bfloat16(v2 - __bfloat162float(h2));
                __nv_bfloat16 l3 = __float2bfloat16(v3 - __bfloat162float(h3));
                size_t plo_i = (size_t)hcur * BH + (size_t)rlo * H_DIM + col;
                size_t phi_i = (size_t)hcur * BH + (size_t)rhi2 * H_DIM + col;
                *(uint32_t*)(hhi + plo_i) =
                    (uint32_t)__bfloat16_as_ushort(h0) | ((uint32_t)__bfloat16_as_ushort(h1) << 16);
                *(uint32_t*)(hhi + phi_i) =
                    (uint32_t)__bfloat16_as_ushort(h2) | ((uint32_t)__bfloat16_as_ushort(h3) << 16);
                *(uint32_t*)(hlo + plo_i) =
                    (uint32_t)__bfloat16_as_ushort(l0) | ((uint32_t)__bfloat16_as_ushort(l1) << 16);
                *(uint32_t*)(hlo + phi_i) =
                    (uint32_t)__bfloat16_as_ushort(l2) | ((uint32_t)__bfloat16_as_ushort(l3) << 16);
            }
        }

        if (t + 1 < steps) {
            __threadfence();
            __syncthreads();
            target += 128;
            if (tid == 0) {
                atomicAdd(&g_bar, 1u);
                while (*vb < target) __nanosleep(64);
            }
            __syncthreads();
        }
    }
#undef ISSUE
}

// ---------------- launch ----------------------------------------------------
extern "C" void kernel_launch(void* const* d_in, const int* in_sizes, int n_in,
                              void* d_out, int out_size)
{
    (void)in_sizes; (void)n_in; (void)out_size;
    const float* x   = (const float*)d_in[0];
    const float* Wi0 = (const float*)d_in[1];
    const float* Wh0 = (const float*)d_in[2];
    const float* Ws0 = (const float*)d_in[3];
    const float* Wi1 = (const float*)d_in[4];
    const float* Wh1 = (const float*)d_in[5];
    const float* Ws1 = (const float*)d_in[6];
    float* out = (float*)d_out;

    void* p;
    cudaGetSymbolAddress(&p, g_pre);     float* pre = (float*)p;
    cudaGetSymbolAddress(&p, g_sx1);     float* sx1 = (float*)p;
    cudaGetSymbolAddress(&p, g_hhi);     __nv_bfloat16* hhi = (__nv_bfloat16*)p;
    cudaGetSymbolAddress(&p, g_hlo);     __nv_bfloat16* hlo = (__nv_bfloat16*)p;
    cudaGetSymbolAddress(&p, g_w0t_hi);  __nv_bfloat16* w0hi = (__nv_bfloat16*)p;
    cudaGetSymbolAddress(&p, g_w0t_lo);  __nv_bfloat16* w0lo = (__nv_bfloat16*)p;
    cudaGetSymbolAddress(&p, g_wi1t_hi); __nv_bfloat16* wi1hi = (__nv_bfloat16*)p;
    cudaGetSymbolAddress(&p, g_wi1t_lo); __nv_bfloat16* wi1lo = (__nv_bfloat16*)p;
    cudaGetSymbolAddress(&p, g_ws1t_hi); __nv_bfloat16* ws1hi = (__nv_bfloat16*)p;
    cudaGetSymbolAddress(&p, g_ws1t_lo); __nv_bfloat16* ws1lo = (__nv_bfloat16*)p;

    cudaFuncSetAttribute(recur2,
                         cudaFuncAttributeMaxDynamicSharedMemorySize, SM2_BYTES);
    cudaFuncSetAttribute(tc_gemm,
                         cudaFuncAttributeMaxDynamicSharedMemorySize,
                         SM_TOTAL_BF16 * 2);

    // weight prep: transpose + bf16 hi/lo split
    dim3 tb(32, 8);
    k_tsplit<<<dim3(I_DIM / 32, H_DIM / 32), tb>>>(Wi0, Ws0, w0hi, w0lo, I_DIM, H_DIM);
    k_tsplit<<<dim3(H_DIM / 32, H_DIM / 32), tb>>>(Wi1, nullptr, wi1hi, wi1lo, H_DIM, H_DIM);
    k_tsplit<<<dim3(I_DIM / 32, H_DIM / 32), tb>>>(Ws1, nullptr, ws1hi, ws1lo, I_DIM, H_DIM);

    // layer 0: pre0 = x @ (Wi0+Ws0)
    tc_gemm<<<dim3(H_DIM / 128, (T_DIM * B_DIM) / 128), 256, SM_TOTAL_BF16 * 2>>>(
        pre, x, I_DIM, w0hi, w0lo, nullptr, 0, nullptr, nullptr);

    k_reset_bar<<<1, 1>>>();
    recur2<<<128, 256, SM2_BYTES>>>(pre, out, Wh0, hhi, hlo, T_DIM);

    // layer 1: pre1 = out0[1:] @ Wi1 + sx1 @ Ws1  (fused)
    int nsx = (T_DIM - 1) * B_DIM * I_DIM;
    k_sx1<<<(nsx + 255) / 256, 256>>>(x, sx1, nsx, B_DIM * I_DIM);
    tc_gemm<<<dim3(H_DIM / 128, ((T_DIM - 1) * B_DIM) / 128), 256, SM_TOTAL_BF16 * 2>>>(
        pre, out + BH, H_DIM, wi1hi, wi1lo, sx1, I_DIM, ws1hi, ws1lo);

    k_reset_bar<<<1, 1>>>();
    recur2<<<128, 256, SM2_BYTES>>>(pre, out + (size_t)T_DIM * BH, Wh1, hhi, hlo, T_DIM - 1);
}

// round 8
// speedup vs baseline: 2.6882x; 1.1607x over previous
#include <cuda_runtime.h>
#include <cuda_bf16.h>
#include <cstdint>

// Problem constants
#define T_DIM 512
#define B_DIM 128
#define I_DIM 512
#define H_DIM 1024
#define BH (B_DIM * H_DIM)

// ---------------- scratch (static device globals: allocation-free) ----------
__device__ float g_pre[T_DIM * B_DIM * H_DIM];            // 268 MB, reused
__device__ float g_sx1[(T_DIM - 1) * B_DIM * I_DIM];      // layer-1 scaled input
__device__ unsigned g_bar4[4 * 64];                       // per-rowgroup barrier counters
// h state as pre-split bf16, double-buffered across steps
__device__ __nv_bfloat16 g_hhi[2 * BH], g_hlo[2 * BH];
// transposed + bf16-split weights: [N][K] row-major, K contiguous
__device__ __nv_bfloat16 g_w0t_hi[H_DIM * I_DIM], g_w0t_lo[H_DIM * I_DIM];
__device__ __nv_bfloat16 g_wi1t_hi[H_DIM * H_DIM], g_wi1t_lo[H_DIM * H_DIM];
__device__ __nv_bfloat16 g_ws1t_hi[H_DIM * I_DIM], g_ws1t_lo[H_DIM * I_DIM];

// ---------------- cp.async helpers -----------------------------------------
__device__ __forceinline__ void cp_async16(void* sdst, const void* gsrc) {
    unsigned s = (unsigned)__cvta_generic_to_shared(sdst);
    asm volatile("cp.async.cg.shared.global [%0], [%1], 16;" :: "r"(s), "l"(gsrc));
}
__device__ __forceinline__ void cp_commit() {
    asm volatile("cp.async.commit_group;" ::: "memory");
}
template <int N>
__device__ __forceinline__ void cp_wait() {
    asm volatile("cp.async.wait_group %0;" :: "n"(N) : "memory");
}

__device__ __forceinline__ void mma_bf16(float* c, const uint32_t* a, const uint32_t* b) {
    asm volatile(
        "mma.sync.aligned.m16n8k16.row.col.f32.bf16.bf16.f32 "
        "{%0,%1,%2,%3}, {%4,%5,%6,%7}, {%8,%9}, {%0,%1,%2,%3};"
        : "+f"(c[0]), "+f"(c[1]), "+f"(c[2]), "+f"(c[3])
        : "r"(a[0]), "r"(a[1]), "r"(a[2]), "r"(a[3]), "r"(b[0]), "r"(b[1]));
}

// ---------------- small elementwise kernels --------------------------------
__global__ void k_sx1(const float* __restrict__ x, float* __restrict__ o,
                      int n, int off) {
    int i = blockIdx.x * 256 + threadIdx.x;
    if (i < n) o[i] = 0.5f * (x[i] + x[i + off]);
}
__global__ void k_reset_bar() {
    if (threadIdx.x < 4 * 64) g_bar4[threadIdx.x] = 0u;
}

// transpose + bf16 hi/lo split: W[K,N] (+optional W2) -> Thi/Tlo [N,K]
__global__ void k_tsplit(const float* __restrict__ W, const float* __restrict__ W2,
                         __nv_bfloat16* __restrict__ Thi, __nv_bfloat16* __restrict__ Tlo,
                         int K, int N) {
    __shared__ float s[32][33];
    int k0 = blockIdx.x * 32, n0 = blockIdx.y * 32;
    int tx = threadIdx.x, ty = threadIdx.y;   // 32 x 8
#pragma unroll
    for (int i = 0; i < 4; i++) {
        int k = k0 + ty + i * 8;
        float v = W[(size_t)k * N + n0 + tx];
        if (W2) v += W2[(size_t)k * N + n0 + tx];
        s[ty + i * 8][tx] = v;
    }
    __syncthreads();
#pragma unroll
    for (int i = 0; i < 4; i++) {
        int n = n0 + ty + i * 8;
        float v = s[tx][ty + i * 8];
        __nv_bfloat16 h = __float2bfloat16(v);
        Thi[(size_t)n * K + k0 + tx] = h;
        Tlo[(size_t)n * K + k0 + tx] = __float2bfloat16(v - __bfloat162float(h));
    }
}

// ---------------- HMMA split-bf16 GEMM (unchanged, proven R4) ---------------
#define PITCH 40
#define TILE_HL (128 * PITCH)
#define SM_A 0
#define SM_B (4 * TILE_HL)
#define SM_TOTAL_BF16 (8 * TILE_HL)

__global__ __launch_bounds__(256) void tc_gemm(
    float* __restrict__ C,
    const float* __restrict__ A0, int K0,
    const __nv_bfloat16* __restrict__ B0hi, const __nv_bfloat16* __restrict__ B0lo,
    const float* __restrict__ A1, int K1,
    const __nv_bfloat16* __restrict__ B1hi, const __nv_bfloat16* __restrict__ B1lo)
{
    extern __shared__ __align__(16) __nv_bfloat16 sm[];
    const int tid = threadIdx.x;
    const int wid = tid >> 5, lane = tid & 31;
    const int g = lane >> 2, tg = lane & 3;
    const int wm = (wid >> 2) * 64, wn = (wid & 3) * 32;
    const int mrow0 = blockIdx.y * 128;
    const int ncol0 = blockIdx.x * 128;

    const int NI0 = K0 / 32;
    const int NI = NI0 + K1 / 32;

    float acc[4][4][4];
#pragma unroll
    for (int i = 0; i < 4; i++)
#pragma unroll
        for (int j = 0; j < 4; j++)
#pragma unroll
            for (int q = 0; q < 4; q++) acc[i][j][q] = 0.f;

    const int ar = tid >> 1, ah = (tid & 1) * 16;
    const int bhl = tid >> 7, br = tid & 127;

#define A_SRC(A, K, koff) ((const float4*)((A) + (size_t)(mrow0 + ar) * (K) + (koff) + ah))
#define STS_A(buf, st)                                                                 \
    {                                                                                  \
        __nv_bfloat16* dh = sm + SM_A + ((buf) * 2 + 0) * TILE_HL + ar * PITCH + ah;   \
        __nv_bfloat16* dl = sm + SM_A + ((buf) * 2 + 1) * TILE_HL + ar * PITCH + ah;   \
        _Pragma("unroll")                                                              \
        for (int q = 0; q < 4; q++) {                                                  \
            float f[4] = {st[q].x, st[q].y, st[q].z, st[q].w};                         \
            uint32_t hi2[2], lo2[2];                                                   \
            _Pragma("unroll")                                                          \
            for (int j = 0; j < 2; j++) {                                              \
                __nv_bfloat16 h0 = __float2bfloat16(f[2 * j]);                         \
                __nv_bfloat16 h1 = __float2bfloat16(f[2 * j + 1]);                     \
                __nv_bfloat16 l0 = __float2bfloat16(f[2 * j] - __bfloat162float(h0));  \
                __nv_bfloat16 l1 = __float2bfloat16(f[2 * j + 1] - __bfloat162float(h1)); \
                hi2[j] = (uint32_t)__bfloat16_as_ushort(h0) |                          \
                         ((uint32_t)__bfloat16_as_ushort(h1) << 16);                   \
                lo2[j] = (uint32_t)__bfloat16_as_ushort(l0) |                          \
                         ((uint32_t)__bfloat16_as_ushort(l1) << 16);                   \
            }                                                                          \
            *(uint2*)(dh + q * 4) = make_uint2(hi2[0], hi2[1]);                        \
            *(uint2*)(dl + q * 4) = make_uint2(lo2[0], lo2[1]);                        \
        }                                                                              \
    }
#define LOAD_B(buf, Bhi, Blo, K, koff)                                                 \
    {                                                                                  \
        const __nv_bfloat16* src = ((bhl) ? (Blo) : (Bhi)) +                           \
                                   (size_t)(ncol0 + br) * (K) + (koff);                \
        __nv_bfloat16* dst = sm + SM_B + ((buf) * 2 + bhl) * TILE_HL + br * PITCH;     \
        _Pragma("unroll")                                                              \
        for (int q = 0; q < 4; q++) cp_async16(dst + q * 8, src + q * 8);              \
    }

    {
        float4 st[4];
        const float4* s4 = A_SRC(A0, K0, 0);
#pragma unroll
        for (int q = 0; q < 4; q++) st[q] = s4[q];
        STS_A(0, st);
        LOAD_B(0, B0hi, B0lo, K0, 0);
        cp_commit();
    }

    for (int i = 0; i < NI; i++) {
        cp_wait<0>();
        __syncthreads();

        const int buf = i & 1;
        float4 st[4];
        bool have_next = (i + 1 < NI);
        if (have_next) {
            int ni = i + 1;
            if (ni < NI0) {
                const float4* s4 = A_SRC(A0, K0, ni * 32);
#pragma unroll
                for (int q = 0; q < 4; q++) st[q] = s4[q];
                LOAD_B(buf ^ 1, B0hi, B0lo, K0, ni * 32);
            } else {
                int koff = (ni - NI0) * 32;
                const float4* s4 = A_SRC(A1, K1, koff);
#pragma unroll
                for (int q = 0; q < 4; q++) st[q] = s4[q];
                LOAD_B(buf ^ 1, B1hi, B1lo, K1, koff);
            }
            cp_commit();
        }

        const __nv_bfloat16* sAh = sm + SM_A + (buf * 2 + 0) * TILE_HL;
        const __nv_bfloat16* sAl = sm + SM_A + (buf * 2 + 1) * TILE_HL;
        const __nv_bfloat16* sBh = sm + SM_B + (buf * 2 + 0) * TILE_HL;
        const __nv_bfloat16* sBl = sm + SM_B + (buf * 2 + 1) * TILE_HL;
#pragma unroll
        for (int kk = 0; kk < 32; kk += 16) {
            uint32_t bh[4][2], bl[4][2];
#pragma unroll
            for (int nt = 0; nt < 4; nt++) {
                int n = wn + nt * 8 + g;
                bh[nt][0] = *(const uint32_t*)(sBh + n * PITCH + kk + tg * 2);
                bh[nt][1] = *(const uint32_t*)(sBh + n * PITCH + kk + tg * 2 + 8);
                bl[nt][0] = *(const uint32_t*)(sBl + n * PITCH + kk + tg * 2);
                bl[nt][1] = *(const uint32_t*)(sBl + n * PITCH + kk + tg * 2 + 8);
            }
#pragma unroll
            for (int mt = 0; mt < 4; mt++) {
                int r = wm + mt * 16 + g;
                uint32_t a_hi[4], a_lo[4];
                a_hi[0] = *(const uint32_t*)(sAh + r * PITCH + kk + tg * 2);
                a_hi[1] = *(const uint32_t*)(sAh + (r + 8) * PITCH + kk + tg * 2);
                a_hi[2] = *(const uint32_t*)(sAh + r * PITCH + kk + tg * 2 + 8);
                a_hi[3] = *(const uint32_t*)(sAh + (r + 8) * PITCH + kk + tg * 2 + 8);
                a_lo[0] = *(const uint32_t*)(sAl + r * PITCH + kk + tg * 2);
                a_lo[1] = *(const uint32_t*)(sAl + (r + 8) * PITCH + kk + tg * 2);
                a_lo[2] = *(const uint32_t*)(sAl + r * PITCH + kk + tg * 2 + 8);
                a_lo[3] = *(const uint32_t*)(sAl + (r + 8) * PITCH + kk + tg * 2 + 8);
#pragma unroll
                for (int nt = 0; nt < 4; nt++) {
                    mma_bf16(acc[mt][nt], a_hi, bh[nt]);
                    mma_bf16(acc[mt][nt], a_lo, bh[nt]);
                    mma_bf16(acc[mt][nt], a_hi, bl[nt]);
                }
            }
        }

        if (have_next) STS_A(buf ^ 1, st);
    }

#pragma unroll
    for (int mt = 0; mt < 4; mt++) {
#pragma unroll
        for (int nt = 0; nt < 4; nt++) {
            int r0 = mrow0 + wm + mt * 16 + g;
            int c0 = ncol0 + wn + nt * 8 + tg * 2;
            *(float2*)(C + (size_t)r0 * 1024 + c0) =
                make_float2(acc[mt][nt][0], acc[mt][nt][1]);
            *(float2*)(C + (size_t)(r0 + 8) * 1024 + c0) =
                make_float2(acc[mt][nt][2], acc[mt][nt][3]);
        }
    }
#undef A_SRC
#undef STS_A
#undef LOAD_B
}

// ---------------- HMMA persistent recurrence v3 ------------------------------
// 128 blocks, 32x32 output tile each (rg = bid>>5 over batch, cg = bid&31 over H).
// 8 warps, each a FULL 32x32 warp tile over a K=128 slice (kg = wid); cross-warp
// K-reduce via padded SMEM (pitch 34: even -> float2-aligned). Wh strip resident
// in SMEM; h streamed as split bf16 in 2+2 double-buffered K=256 chunks, all
// loads front-issued after the row-group-local barrier (4 counters, 32 arrivals).
#define R3_WP 1032
#define R3_SW (32 * R3_WP)              // 33024 elems
#define R3_HP 264
#define R3_HB (32 * R3_HP)              // 8448 elems
#define R3_HOFF (2 * R3_SW)             // 66048 elems
#define R3_RED_BYTE (R3_HOFF * 2)       // 132096 (aliases h buffer region)
#define R3_RPITCH 34                    // reduce pitch (even -> 8B alignment)
#define R3_RW (32 * R3_RPITCH)          // 1088 floats per warp
#define R3_PRE_BYTE ((R3_HOFF + 4 * R3_HB) * 2)  // 199680
#define R3_BYTES (R3_PRE_BYTE + 4096)   // 203776

__global__ __launch_bounds__(256, 1) void recur3(
    const float* __restrict__ pre, float* __restrict__ out,
    const float* __restrict__ Wh,
    __nv_bfloat16* __restrict__ hhi, __nv_bfloat16* __restrict__ hlo,
    int steps)
{
    extern __shared__ __align__(16) __nv_bfloat16 sm2[];
    float* red  = (float*)((char*)sm2 + R3_RED_BYTE);
    float* preS = (float*)((char*)sm2 + R3_PRE_BYTE);
    const int tid = threadIdx.x, wid = tid >> 5, lane = tid & 31;
    const int g = lane >> 2, tg = lane & 3;
    const int rg = blockIdx.x >> 5;
    const int r0 = rg * 32;
    const int c0 = (blockIdx.x & 31) * 32;

    // ---- load + split Wh strip into SMEM once ----
    for (int k = wid; k < H_DIM; k += 8) {
        float w = Wh[(size_t)k * H_DIM + c0 + lane];
        __nv_bfloat16 h = __float2bfloat16(w);
        sm2[lane * R3_WP + k] = h;
        sm2[R3_SW + lane * R3_WP + k] = __float2bfloat16(w - __bfloat162float(h));
    }
    __syncthreads();

    unsigned target = 0;
    volatile unsigned* vb = &g_bar4[rg * 64];

#define ISSUE_H(c, buf, hp)                                                              \
    {                                                                                    \
        _Pragma("unroll")                                                                \
        for (int i = 0; i < 8; i++) {                                                    \
            int f = i * 256 + tid;                                                       \
            int hl = f >> 10, rem = f & 1023;                                            \
            int row = rem >> 5, seg = rem & 31;                                          \
            const __nv_bfloat16* src = (hl ? hlo : hhi) + (size_t)(hp)*BH +              \
                                       (size_t)(r0 + row) * H_DIM + (c)*256 + seg * 8;   \
            cp_async16(sm2 + R3_HOFF + ((buf)*2 + hl) * R3_HB + row * R3_HP + seg * 8,   \
                       src);                                                             \
        }                                                                                \
        cp_commit();                                                                     \
    }
#define ISSUE_PRE(tt)                                                                    \
    {                                                                                    \
        int row = tid >> 3, seg = tid & 7;                                               \
        cp_async16(preS + row * 32 + seg * 4,                                            \
                   pre + (size_t)(tt)*BH + (size_t)(r0 + row) * H_DIM + c0 + seg * 4);   \
        cp_commit();                                                                     \
    }

    for (int t = 0; t < steps; t++) {
        float acc[2][4][4];
#pragma unroll
        for (int mt = 0; mt < 2; mt++)
#pragma unroll
            for (int nt = 0; nt < 4; nt++)
#pragma unroll
                for (int q = 0; q < 4; q++) acc[mt][nt][q] = 0.f;

        if (t > 0) {
            const int hp = (t - 1) & 1;
            ISSUE_H(0, 0, hp);
            ISSUE_H(1, 1, hp);
            ISSUE_PRE(t);
#pragma unroll 1
            for (int c = 0; c < 4; c++) {
                if (c <= 1) cp_wait<2>();
                else if (c == 2) cp_wait<1>();
                else cp_wait<0>();
                __syncthreads();
                const int buf = c & 1;
                const __nv_bfloat16* sAh = sm2 + R3_HOFF + buf * 2 * R3_HB;
                const __nv_bfloat16* sAl = sAh + R3_HB;
                const int kl = wid * 32;
#pragma unroll
                for (int kt = 0; kt < 2; kt++) {
                    const int kk = kl + kt * 16;
                    const int kgl = c * 256 + kk;
                    uint32_t ah[2][4], al[2][4];
#pragma unroll
                    for (int mt = 0; mt < 2; mt++) {
                        const int ra = (mt * 16 + g) * R3_HP + kk + tg * 2;
                        const int rb = (mt * 16 + g + 8) * R3_HP + kk + tg * 2;
                        ah[mt][0] = *(const uint32_t*)(sAh + ra);
                        ah[mt][1] = *(const uint32_t*)(sAh + rb);
                        ah[mt][2] = *(const uint32_t*)(sAh + ra + 8);
                        ah[mt][3] = *(const uint32_t*)(sAh + rb + 8);
                        al[mt][0] = *(const uint32_t*)(sAl + ra);
                        al[mt][1] = *(const uint32_t*)(sAl + rb);
                        al[mt][2] = *(const uint32_t*)(sAl + ra + 8);
                        al[mt][3] = *(const uint32_t*)(sAl + rb + 8);
                    }
#pragma unroll
                    for (int nt = 0; nt < 4; nt++) {
                        const int nb = (nt * 8 + g) * R3_WP + kgl + tg * 2;
                        uint32_t bh[2], bl[2];
                        bh[0] = *(const uint32_t*)(sm2 + nb);
                        bh[1] = *(const uint32_t*)(sm2 + nb + 8);
                        bl[0] = *(const uint32_t*)(sm2 + R3_SW + nb);
                        bl[1] = *(const uint32_t*)(sm2 + R3_SW + nb + 8);
#pragma unroll
                        for (int mt = 0; mt < 2; mt++) {
                            mma_bf16(acc[mt][nt], ah[mt], bh);
                            mma_bf16(acc[mt][nt], al[mt], bh);
                            mma_bf16(acc[mt][nt], ah[mt], bl);
                        }
                    }
                }
                __syncthreads();
                if (c < 2) ISSUE_H(c + 2, c & 1, hp);
            }
            // ---- write partials for cross-warp K reduction (pitch 34, aligned) ----
            float* rw = red + wid * R3_RW;
#pragma unroll
            for (int mt = 0; mt < 2; mt++)
#pragma unroll
                for (int nt = 0; nt < 4; nt++) {
                    int row = mt * 16 + g, col = nt * 8 + tg * 2;
                    *(float2*)(rw + row * R3_RPITCH + col) =
                        make_float2(acc[mt][nt][0], acc[mt][nt][1]);
                    *(float2*)(rw + (row + 8) * R3_RPITCH + col) =
                        make_float2(acc[mt][nt][2], acc[mt][nt][3]);
                }
            __syncthreads();
        } else {
            ISSUE_PRE(0);
            cp_wait<0>();
            __syncthreads();
        }

        // ---- reduce + epilogue: 4 outputs per thread ----
        {
            const int row = tid >> 3, cseg = (tid & 7) * 4;
            float4 s = make_float4(0.f, 0.f, 0.f, 0.f);
            if (t > 0) {
#pragma unroll
                for (int w = 0; w < 8; w++) {
                    const float* rp = red + w * R3_RW + row * R3_RPITCH + cseg;
                    s.x += rp[0]; s.y += rp[1]; s.z += rp[2]; s.w += rp[3];
                }
            }
            const float4 p = *(const float4*)(preS + row * 32 + cseg);
            float v0 = tanhf(p.x + s.x), v1 = tanhf(p.y + s.y);
            float v2 = tanhf(p.z + s.z), v3 = tanhf(p.w + s.w);
            const size_t gidx = (size_t)(r0 + row) * H_DIM + c0 + cseg;
            *(float4*)(out + (size_t)t * BH + gidx) = make_float4(v0, v1, v2, v3);

            __nv_bfloat16 h0 = __float2bfloat16(v0), h1 = __float2bfloat16(v1);
            __nv_bfloat16 h2 = __float2bfloat16(v2), h3 = __float2bfloat16(v3);
            __nv_bfloat16 l0 = __float2bfloat16(v0 - __bfloat162float(h0));
            __nv_bfloat16 l1 = __float2bfloat16(v1 - __bfloat162float(h1));
            __nv_bfloat16 l2 = __float2bfloat16(v2 - __bfloat162float(h2));
            __nv_bfloat16 l3 = __float2bfloat16(v3 - __bfloat162float(h3));
            const size_t hidx = (size_t)(t & 1) * BH + gidx;
            *(uint2*)(hhi + hidx) = make_uint2(
                (uint32_t)__bfloat16_as_ushort(h0) | ((uint32_t)__bfloat16_as_ushort(h1) << 16),
                (uint32_t)__bfloat16_as_ushort(h2) | ((uint32_t)__bfloat16_as_ushort(h3) << 16));
            *(uint2*)(hlo + hidx) = make_uint2(
                (uint32_t)__bfloat16_as_ushort(l0) | ((uint32_t)__bfloat16_as_ushort(l1) << 16),
                (uint32_t)__bfloat16_as_ushort(l2) | ((uint32_t)__bfloat16_as_ushort(l3) << 16));
        }

        if (t + 1 < steps) {
            __threadfence();
            __syncthreads();
            target += 32;
            if (tid == 0) {
                atomicAdd((unsigned*)vb, 1u);
                while (*vb < target) __nanosleep(32);
            }
            __syncthreads();
        }
    }
#undef ISSUE_H
#undef ISSUE_PRE
}

// ---------------- launch ----------------------------------------------------
extern "C" void kernel_launch(void* const* d_in, const int* in_sizes, int n_in,
                              void* d_out, int out_size)
{
    (void)in_sizes; (void)n_in; (void)out_size;
    const float* x   = (const float*)d_in[0];
    const float* Wi0 = (const float*)d_in[1];
    const float* Wh0 = (const float*)d_in[2];
    const float* Ws0 = (const float*)d_in[3];
    const float* Wi1 = (const float*)d_in[4];
    const float* Wh1 = (const float*)d_in[5];
    const float* Ws1 = (const float*)d_in[6];
    float* out = (float*)d_out;

    void* p;
    cudaGetSymbolAddress(&p, g_pre);     float* pre = (float*)p;
    cudaGetSymbolAddress(&p, g_sx1);     float* sx1 = (float*)p;
    cudaGetSymbolAddress(&p, g_hhi);     __nv_bfloat16* hhi = (__nv_bfloat16*)p;
    cudaGetSymbolAddress(&p, g_hlo);     __nv_bfloat16* hlo = (__nv_bfloat16*)p;
    cudaGetSymbolAddress(&p, g_w0t_hi);  __nv_bfloat16* w0hi = (__nv_bfloat16*)p;
    cudaGetSymbolAddress(&p, g_w0t_lo);  __nv_bfloat16* w0lo = (__nv_bfloat16*)p;
    cudaGetSymbolAddress(&p, g_wi1t_hi); __nv_bfloat16* wi1hi = (__nv_bfloat16*)p;
    cudaGetSymbolAddress(&p, g_wi1t_lo); __nv_bfloat16* wi1lo = (__nv_bfloat16*)p;
    cudaGetSymbolAddress(&p, g_ws1t_hi); __nv_bfloat16* ws1hi = (__nv_bfloat16*)p;
    cudaGetSymbolAddress(&p, g_ws1t_lo); __nv_bfloat16* ws1lo = (__nv_bfloat16*)p;

    cudaFuncSetAttribute(recur3,
                         cudaFuncAttributeMaxDynamicSharedMemorySize, R3_BYTES);
    cudaFuncSetAttribute(tc_gemm,
                         cudaFuncAttributeMaxDynamicSharedMemorySize,
                         SM_TOTAL_BF16 * 2);

    // weight prep: transpose + bf16 hi/lo split
    dim3 tb(32, 8);
    k_tsplit<<<dim3(I_DIM / 32, H_DIM / 32), tb>>>(Wi0, Ws0, w0hi, w0lo, I_DIM, H_DIM);
    k_tsplit<<<dim3(H_DIM / 32, H_DIM / 32), tb>>>(Wi1, nullptr, wi1hi, wi1lo, H_DIM, H_DIM);
    k_tsplit<<<dim3(I_DIM / 32, H_DIM / 32), tb>>>(Ws1, nullptr, ws1hi, ws1lo, I_DIM, H_DIM);

    // layer 0: pre0 = x @ (Wi0+Ws0)
    tc_gemm<<<dim3(H_DIM / 128, (T_DIM * B_DIM) / 128), 256, SM_TOTAL_BF16 * 2>>>(
        pre, x, I_DIM, w0hi, w0lo, nullptr, 0, nullptr, nullptr);

    k_reset_bar<<<1, 256>>>();
    recur3<<<128, 256, R3_BYTES>>>(pre, out, Wh0, hhi, hlo, T_DIM);

    // layer 1: pre1 = out0[1:] @ Wi1 + sx1 @ Ws1  (fused)
    int nsx = (T_DIM - 1) * B_DIM * I_DIM;
    k_sx1<<<(nsx + 255) / 256, 256>>>(x, sx1, nsx, B_DIM * I_DIM);
    tc_gemm<<<dim3(H_DIM / 128, ((T_DIM - 1) * B_DIM) / 128), 256, SM_TOTAL_BF16 * 2>>>(
        pre, out + BH, H_DIM, wi1hi, wi1lo, sx1, I_DIM, ws1hi, ws1lo);

    k_reset_bar<<<1, 256>>>();
    recur3<<<128, 256, R3_BYTES>>>(pre, out + (size_t)T_DIM * BH, Wh1, hhi, hlo, T_DIM - 1);
}